// round 15
// baseline (speedup 1.0000x reference)
#include <cuda_runtime.h>
#include <cuda_fp16.h>
#include <cstdint>

#define L_SEQ 1024
#define BATCH_BS 8
#define EMB 512
#define O3 1536
#define NB 64            // BATCH_BS * NH

// Q pre-scale: exp(0.125*s) = exp2(s * 0.125 * log2(e))
#define QSCALE 0.18033688011112042f

// Scratch (device globals)
__device__ __half g_Ah[(size_t)8192 * EMB];       // emb as fp16, 8 MB
__device__ __half g_Bh[(size_t)O3 * EMB];         // W_qkv as fp16, 1.5 MB
__device__ __half g_Q[(size_t)NB * L_SEQ * 64];   // 8 MB (pre-scaled by QSCALE)
__device__ __half g_K[(size_t)NB * L_SEQ * 64];   // 8 MB
__device__ float  g_V[(size_t)NB * L_SEQ * 64];   // 16 MB
__device__ float  g_Z[NB * L_SEQ];                // raw row sums (atomic)
__device__ float  g_W[NB * L_SEQ];                // attn weights (atomic)
__device__ float  g_P[NB * 8 * 64];               // k4a partials

// ---------------------------------------------------------------------------
// helpers
// ---------------------------------------------------------------------------
__device__ __forceinline__ uint32_t f22h2(float lo, float hi) {
    __half2 h = __floats2half2_rn(lo, hi);
    return reinterpret_cast<uint32_t&>(h);
}
__device__ __forceinline__ uint32_t smem_u32(const void* p) {
    return (uint32_t)__cvta_generic_to_shared(p);
}
__device__ __forceinline__ float frcp(float x) {
    float r;
    asm("rcp.approx.f32 %0, %1;" : "=f"(r) : "f"(x));
    return r;
}
// pack two fp32 -> fp16x2, exp2 both with ONE MUFU op; result stays packed
__device__ __forceinline__ uint32_t ex2h2(float a, float b) {
    uint32_t p = f22h2(a, b), e;
    asm("ex2.approx.f16x2 %0, %1;" : "=r"(e) : "r"(p));
    return e;
}
__device__ __forceinline__ void ldsm4(uint32_t& r0, uint32_t& r1,
                                      uint32_t& r2, uint32_t& r3,
                                      const __half* p) {
    uint32_t addr = smem_u32(p);
    asm volatile("ldmatrix.sync.aligned.m8n8.x4.shared.b16 {%0,%1,%2,%3}, [%4];"
                 : "=r"(r0), "=r"(r1), "=r"(r2), "=r"(r3) : "r"(addr));
}
__device__ __forceinline__ void mma_f16(float* d, const uint32_t* a, const uint32_t* b) {
    asm volatile(
        "mma.sync.aligned.m16n8k16.row.col.f32.f16.f16.f32 "
        "{%0,%1,%2,%3}, {%4,%5,%6,%7}, {%8,%9}, {%0,%1,%2,%3};\n"
        : "+f"(d[0]), "+f"(d[1]), "+f"(d[2]), "+f"(d[3])
        : "r"(a[0]), "r"(a[1]), "r"(a[2]), "r"(a[3]), "r"(b[0]), "r"(b[1]));
}

// ---------------------------------------------------------------------------
// KC: one-time fp32 -> fp16 convert of emb + W_qkv; zero Z and W.
// ---------------------------------------------------------------------------
__global__ void __launch_bounds__(1024) kcvt(
    const float* __restrict__ A, const float* __restrict__ B)
{
    const size_t i = (size_t)blockIdx.x * 1024 + threadIdx.x;
    if (i < 1048576) {
        const float4 v = ((const float4*)A)[i];
        ((uint2*)g_Ah)[i] = make_uint2(f22h2(v.x, v.y), f22h2(v.z, v.w));
    } else {
        const size_t j = i - 1048576;
        const float4 v = ((const float4*)B)[j];
        ((uint2*)g_Bh)[j] = make_uint2(f22h2(v.x, v.y), f22h2(v.z, v.w));
    }
    if (i < NB * L_SEQ) {
        g_Z[i] = 0.0f;
        g_W[i] = 0.0f;
    }
}

// ---------------------------------------------------------------------------
// K1: C = emb_h[8192,512] @ W_h[1536,512]^T + bias  (fp16 mma, NT)
// double-buffered smem mainloop; epilogue stages Q/K output halves in smem
// and flushes them as fully-coalesced 128B segments (each 64-aligned column
// section maps to one contiguous 64-half run per row in g_Q/g_K). V halves
// stay fp32 and take the direct scattered path.
// ---------------------------------------------------------------------------
#define SA 40
#define SG 72    // staging stride (halves)
__global__ void __launch_bounds__(256) k1_qkv(const float* __restrict__ bias)
{
    // one pool: mainloop uses it as As[2]|Bs[2]; epilogue reuses it as staging
    __shared__ __half SM[4 * 128 * SA];          // 40 KB
    __half* As0 = SM;
    __half* As1 = SM + 128 * SA;
    __half* Bs0 = SM + 2 * 128 * SA;
    __half* Bs1 = SM + 3 * 128 * SA;
    __half* Ssm = SM;                            // staging: 2 * 128 * SG = 18432 halves

    const int tid  = threadIdx.x;
    const int warp = tid >> 5;
    const int lane = tid & 31;
    const int g = lane >> 2, t = lane & 3;
    const int wm0 = (warp >> 2) * 64;
    const int wn0 = (warp & 3) * 32;
    const int m0 = blockIdx.y * 128;
    const int n0 = blockIdx.x * 128;

    const int lrow = tid >> 1;
    const int lk   = (tid & 1) * 16;
    const __half* ap = g_Ah + (size_t)(m0 + lrow) * EMB + lk;
    const __half* bp = g_Bh + (size_t)(n0 + lrow) * EMB + lk;

    const int lm = lane & 15;
    const int lc = (lane >> 4) * 8;

    float acc[4][4][4];
#pragma unroll
    for (int i = 0; i < 4; i++)
#pragma unroll
        for (int j = 0; j < 4; j++)
#pragma unroll
            for (int c = 0; c < 4; c++) acc[i][j][c] = 0.0f;

    uint4 a0 = *(const uint4*)(ap);
    uint4 a1 = *(const uint4*)(ap + 8);
    uint4 b0 = *(const uint4*)(bp);
    uint4 b1 = *(const uint4*)(bp + 8);
    *(uint4*)(As0 + lrow * SA + lk)     = a0;
    *(uint4*)(As0 + lrow * SA + lk + 8) = a1;
    *(uint4*)(Bs0 + lrow * SA + lk)     = b0;
    *(uint4*)(Bs0 + lrow * SA + lk + 8) = b1;

#pragma unroll 4
    for (int s = 0; s < 16; s++) {
        if (s < 15) {
            const int nk = (s + 1) * 32;
            a0 = *(const uint4*)(ap + nk);
            a1 = *(const uint4*)(ap + nk + 8);
            b0 = *(const uint4*)(bp + nk);
            b1 = *(const uint4*)(bp + nk + 8);
        }
        __syncthreads();
        const __half* Ab = (s & 1) ? As1 : As0;
        const __half* Bb = (s & 1) ? Bs1 : Bs0;
#pragma unroll
        for (int kk = 0; kk < 32; kk += 16) {
            uint32_t af[4][4];
#pragma unroll
            for (int im = 0; im < 4; im++)
                ldsm4(af[im][0], af[im][1], af[im][2], af[im][3],
                      Ab + (wm0 + im * 16 + lm) * SA + kk + lc);
            uint32_t br0[4], br1[4];
            ldsm4(br0[0], br0[1], br0[2], br0[3], Bb + (wn0 +      lm) * SA + kk + lc);
            ldsm4(br1[0], br1[1], br1[2], br1[3], Bb + (wn0 + 16 + lm) * SA + kk + lc);
            uint32_t bf[4][2] = {{br0[0], br0[2]}, {br0[1], br0[3]},
                                 {br1[0], br1[2]}, {br1[1], br1[3]}};
#pragma unroll
            for (int im = 0; im < 4; im++)
#pragma unroll
                for (int in = 0; in < 4; in++)
                    mma_f16(acc[im][in], af[im], bf[in]);
        }
        if (s < 15) {
            __half* An = (s & 1) ? As0 : As1;
            __half* Bn = (s & 1) ? Bs0 : Bs1;
            *(uint4*)(An + lrow * SA + lk)     = a0;
            *(uint4*)(An + lrow * SA + lk + 8) = a1;
            *(uint4*)(Bn + lrow * SA + lk)     = b0;
            *(uint4*)(Bn + lrow * SA + lk + 8) = b1;
        }
    }

    // ---- epilogue: per-half section classification ----
    // half hf2 covers tile columns [64*hf2, 64*hf2+64): one (head, section)
    int hsec[2], hhead[2];
#pragma unroll
    for (int h2 = 0; h2 < 2; h2++) {
        const int c0 = n0 + 64 * h2;
        hhead[h2] = c0 / 192;
        hsec[h2]  = (c0 - hhead[h2] * 192) >> 6;   // 0=Q 1=K 2=V
    }

    __syncthreads();   // mainloop smem reads done; reuse SM as staging

    // write fragments: Q/K halves -> staging smem (fp16); V half -> gmem direct
#pragma unroll
    for (int im = 0; im < 4; im++) {
        const int rloc0 = wm0 + im * 16 + g;
#pragma unroll
        for (int in = 0; in < 4; in++) {
            const int col  = wn0 + in * 8 + 2 * t;   // tile-local 0..127
            const int h2   = col >> 6;
            const int cloc = col & 63;
            const int sect = hsec[h2];
            const float b0f = __ldg(bias + n0 + col);
            const float b1f = __ldg(bias + n0 + col + 1);
#pragma unroll
            for (int hf = 0; hf < 2; hf++) {
                const int rloc = rloc0 + hf * 8;
                float v0 = acc[im][in][2 * hf    ] + b0f;
                float v1 = acc[im][in][2 * hf + 1] + b1f;
                if (sect == 2) {
                    const int r = m0 + rloc;
                    const int l = r >> 3, bb = r & 7;
                    *(float2*)(g_V + ((size_t)(bb * 8 + hhead[h2]) << 16)
                               + l * 64 + cloc) = make_float2(v0, v1);
                } else {
                    if (sect == 0) { v0 *= QSCALE; v1 *= QSCALE; }
                    *(uint32_t*)(Ssm + h2 * 128 * SG + rloc * SG + cloc)
                        = f22h2(v0, v1);
                }
            }
        }
    }
    __syncthreads();

    // flush staged halves: fully coalesced 128B destination runs.
    // thread -> (row = tid>>1, part = tid&1): copies 64B (4 x uint4).
#pragma unroll
    for (int h2 = 0; h2 < 2; h2++) {
        if (hsec[h2] == 2) continue;
        __half* dstbase = (hsec[h2] == 0) ? g_Q : g_K;
        const int row  = tid >> 1;
        const int part = (tid & 1) * 32;
        const int r = m0 + row;
        const int l = r >> 3, bb = r & 7;
        __half* dst = dstbase + ((size_t)(bb * 8 + hhead[h2]) << 16) + l * 64 + part;
        const __half* src = Ssm + h2 * 128 * SG + row * SG + part;
#pragma unroll
        for (int j = 0; j < 4; j++)
            *(uint4*)(dst + j * 8) = *(const uint4*)(src + j * 8);
    }
}

// ---------------------------------------------------------------------------
// K2: scores (log2 domain) per B, tile 128x128, d=64 in SMEM.
// PASS1: S = Q @ K^T; Z[row] += rowsum(exp2 S) via ones-mma.
// PASS2: S' = K @ Q^T; W[key] += Σ_query exp2(S') * rZ[query] via reduce-mma
//   whose B fragment carries rZ.
// ---------------------------------------------------------------------------
#define SQ 72
template<bool PASS2>
__global__ void __launch_bounds__(256) k2_attn()
{
    __shared__ __half Qs[128 * SQ];
    __shared__ __half Ks[128 * SQ];
    __shared__ float  rsh[128];

    const int tid  = threadIdx.x;
    const int warp = tid >> 5;
    const int lane = tid & 31;
    const int g = lane >> 2, t = lane & 3;
    const int wm0 = (warp >> 2) * 64;
    const int wn0 = (warp & 3) * 32;

    const int B  = blockIdx.z;
    const int n0 = blockIdx.x * 128;    // keys
    const int m0 = blockIdx.y * 128;    // queries

    const __half* qg = g_Q + ((size_t)B << 16) + (size_t)m0 * 64;
    const __half* kg = g_K + ((size_t)B << 16) + (size_t)n0 * 64;

#pragma unroll
    for (int j = 0; j < 4; j++) {
        const int idx = tid + j * 256;
        const int row = idx >> 3;
        const int ch  = (idx & 7) * 8;
        *(uint4*)(Qs + row * SQ + ch) = *(const uint4*)(qg + row * 64 + ch);
        *(uint4*)(Ks + row * SQ + ch) = *(const uint4*)(kg + row * 64 + ch);
    }
    if (PASS2 && tid < 128)
        rsh[tid] = frcp(g_Z[B * 1024 + m0 + tid]);
    __syncthreads();

    const __half* At = PASS2 ? Ks : Qs;
    const __half* Bt = PASS2 ? Qs : Ks;

    const int lm = lane & 15;
    const int lc = (lane >> 4) * 8;

    float acc[4][4][4];
#pragma unroll
    for (int i = 0; i < 4; i++)
#pragma unroll
        for (int j = 0; j < 4; j++)
#pragma unroll
            for (int c = 0; c < 4; c++) acc[i][j][c] = 0.0f;

#pragma unroll
    for (int kk = 0; kk < 64; kk += 16) {
        uint32_t af[4][4];
#pragma unroll
        for (int im = 0; im < 4; im++)
            ldsm4(af[im][0], af[im][1], af[im][2], af[im][3],
                  At + (wm0 + im * 16 + lm) * SQ + kk + lc);
        uint32_t br0[4], br1[4];
        ldsm4(br0[0], br0[1], br0[2], br0[3], Bt + (wn0 +      lm) * SQ + kk + lc);
        ldsm4(br1[0], br1[1], br1[2], br1[3], Bt + (wn0 + 16 + lm) * SQ + kk + lc);
        uint32_t bf[4][2] = {{br0[0], br0[2]}, {br0[1], br0[3]},
                             {br1[0], br1[2]}, {br1[1], br1[3]}};
#pragma unroll
        for (int im = 0; im < 4; im++)
#pragma unroll
            for (int in = 0; in < 4; in++)
                mma_f16(acc[im][in], af[im], bf[in]);
    }

    uint32_t eh[4][4][2];
#pragma unroll
    for (int im = 0; im < 4; im++)
#pragma unroll
        for (int in = 0; in < 4; in++) {
            eh[im][in][0] = ex2h2(acc[im][in][0], acc[im][in][1]);
            eh[im][in][1] = ex2h2(acc[im][in][2], acc[im][in][3]);
        }

    const uint32_t ones2 = 0x3C003C00u;
    uint32_t bz0[2] = {ones2, ones2};
    uint32_t bz1[2] = {ones2, ones2};
    if (PASS2) {
        const int qb = wn0 + 2 * t;
        bz0[0] = f22h2(rsh[qb],      rsh[qb + 1]);
        bz0[1] = f22h2(rsh[qb + 8],  rsh[qb + 9]);
        bz1[0] = f22h2(rsh[qb + 16], rsh[qb + 17]);
        bz1[1] = f22h2(rsh[qb + 24], rsh[qb + 25]);
    }

    float* target = PASS2 ? g_W : g_Z;
    const int rbase = (PASS2 ? n0 : m0) + wm0;

#pragma unroll
    for (int im = 0; im < 4; im++) {
        float rs[4] = {0.0f, 0.0f, 0.0f, 0.0f};
        uint32_t afr0[4] = {eh[im][0][0], eh[im][0][1], eh[im][1][0], eh[im][1][1]};
        mma_f16(rs, afr0, bz0);
        uint32_t afr1[4] = {eh[im][2][0], eh[im][2][1], eh[im][3][0], eh[im][3][1]};
        mma_f16(rs, afr1, bz1);
        if (t == 0) {
            const int row = rbase + im * 16 + g;
            atomicAdd(&target[B * 1024 + row],     rs[0]);
            atomicAdd(&target[B * 1024 + row + 8], rs[2]);
        }
    }
}

// ---------------------------------------------------------------------------
// K4a: partial dot products. grid (8 chunks, 64 B), block 256.
// ---------------------------------------------------------------------------
__global__ void __launch_bounds__(256) k4a_partial()
{
    const int B  = blockIdx.y;
    const int ch = blockIdx.x;
    const int tid = threadIdx.x;
    const int d = tid & 63, mg = tid >> 6;

    const float* vptr = g_V + ((size_t)B << 16) + (size_t)ch * 128 * 64 + d;
    const float* wp   = g_W + B * 1024 + ch * 128;

    float acc = 0.0f;
#pragma unroll 8
    for (int m = mg; m < 128; m += 4)
        acc = fmaf(wp[m], vptr[m * 64], acc);

    __shared__ float sh[4][64];
    sh[mg][d] = acc;
    __syncthreads();
    if (tid < 64)
        g_P[(B * 8 + ch) * 64 + tid] =
            sh[0][tid] + sh[1][tid] + sh[2][tid] + sh[3][tid];
}

// ---------------------------------------------------------------------------
// K4b: reduce 8 partials + GroupNorm + affine + out. grid 64, block 64.
// ---------------------------------------------------------------------------
__global__ void __launch_bounds__(64) k4b_gn(
    const float* __restrict__ gw, const float* __restrict__ gb,
    float* __restrict__ out)
{
    const int B  = blockIdx.x;
    const int bb = B >> 3, hh = B & 7;
    const int tid = threadIdx.x;
    const int lane = tid & 31, wp = tid >> 5;

    float v = 0.0f;
#pragma unroll
    for (int c = 0; c < 8; c++)
        v += g_P[(B * 8 + c) * 64 + tid];

    float s = v, sq = v * v;
#pragma unroll
    for (int o = 16; o > 0; o >>= 1) {
        s  += __shfl_xor_sync(0xffffffffu, s, o);
        sq += __shfl_xor_sync(0xffffffffu, sq, o);
    }
    __shared__ float red[4];
    if (lane == 0) { red[wp * 2] = s; red[wp * 2 + 1] = sq; }
    __syncthreads();
    const float sum = red[0] + red[2];
    const float ssq = red[1] + red[3];
    const float mean = sum * (1.0f / 64.0f);
    const float var  = ssq * (1.0f / 64.0f) - mean * mean;
    out[bb * 512 + hh * 64 + tid] =
        (v - mean) * rsqrtf(var + 1e-5f) * __ldg(gw + hh) + __ldg(gb + hh);
}

// ---------------------------------------------------------------------------
// Launcher (graph-capturable)
// ---------------------------------------------------------------------------
extern "C" void kernel_launch(void* const* d_in, const int* in_sizes, int n_in,
                              void* d_out, int out_size)
{
    (void)in_sizes; (void)n_in; (void)out_size;
    const float* emb = (const float*)d_in[0];
    const float* Wq  = (const float*)d_in[1];
    const float* bq  = (const float*)d_in[2];
    const float* gw  = (const float*)d_in[3];
    const float* gb  = (const float*)d_in[4];
    float* out = (float*)d_out;

    kcvt     <<<1216, 1024>>>(emb, Wq);
    k1_qkv   <<<dim3(12, 64), 256>>>(bq);
    k2_attn<false><<<dim3(8, 8, 64), 256>>>();
    k2_attn<true> <<<dim3(8, 8, 64), 256>>>();
    k4a_partial<<<dim3(8, 64), 256>>>();
    k4b_gn   <<<64, 64>>>(gw, gb, out);
}

// round 16
// speedup vs baseline: 1.0887x; 1.0887x over previous
#include <cuda_runtime.h>
#include <cuda_fp16.h>
#include <cstdint>

#define L_SEQ 1024
#define BATCH_BS 8
#define EMB 512
#define O3 1536
#define NB 64            // BATCH_BS * NH

// Q pre-scale: exp(0.125*s) = exp2(s * 0.125 * log2(e))
#define QSCALE 0.18033688011112042f

// Scratch (device globals)
__device__ __half g_Ah[(size_t)8192 * EMB];       // emb as fp16, 8 MB
__device__ __half g_Bh[(size_t)O3 * EMB];         // W_qkv as fp16, 1.5 MB
__device__ __half g_Q[(size_t)NB * L_SEQ * 64];   // 8 MB (pre-scaled by QSCALE)
__device__ __half g_K[(size_t)NB * L_SEQ * 64];   // 8 MB
__device__ float  g_V[(size_t)NB * L_SEQ * 64];   // 16 MB
__device__ float  g_Z[NB * L_SEQ];                // raw row sums (atomic)
__device__ float  g_W[NB * L_SEQ];                // attn weights (atomic)
__device__ float  g_P[NB * 8 * 64];               // k4a partials

// ---------------------------------------------------------------------------
// helpers
// ---------------------------------------------------------------------------
__device__ __forceinline__ uint32_t f22h2(float lo, float hi) {
    __half2 h = __floats2half2_rn(lo, hi);
    return reinterpret_cast<uint32_t&>(h);
}
__device__ __forceinline__ uint32_t smem_u32(const void* p) {
    return (uint32_t)__cvta_generic_to_shared(p);
}
__device__ __forceinline__ float frcp(float x) {
    float r;
    asm("rcp.approx.f32 %0, %1;" : "=f"(r) : "f"(x));
    return r;
}
// pack two fp32 -> fp16x2, exp2 both with ONE MUFU op; result stays packed
__device__ __forceinline__ uint32_t ex2h2(float a, float b) {
    uint32_t p = f22h2(a, b), e;
    asm("ex2.approx.f16x2 %0, %1;" : "=r"(e) : "r"(p));
    return e;
}
__device__ __forceinline__ void ldsm4(uint32_t& r0, uint32_t& r1,
                                      uint32_t& r2, uint32_t& r3,
                                      const __half* p) {
    uint32_t addr = smem_u32(p);
    asm volatile("ldmatrix.sync.aligned.m8n8.x4.shared.b16 {%0,%1,%2,%3}, [%4];"
                 : "=r"(r0), "=r"(r1), "=r"(r2), "=r"(r3) : "r"(addr));
}
__device__ __forceinline__ void mma_f16(float* d, const uint32_t* a, const uint32_t* b) {
    asm volatile(
        "mma.sync.aligned.m16n8k16.row.col.f32.f16.f16.f32 "
        "{%0,%1,%2,%3}, {%4,%5,%6,%7}, {%8,%9}, {%0,%1,%2,%3};\n"
        : "+f"(d[0]), "+f"(d[1]), "+f"(d[2]), "+f"(d[3])
        : "r"(a[0]), "r"(a[1]), "r"(a[2]), "r"(a[3]), "r"(b[0]), "r"(b[1]));
}

// ---------------------------------------------------------------------------
// KC: one-time fp32 -> fp16 convert of emb + W_qkv; zero Z and W.
// ---------------------------------------------------------------------------
__global__ void __launch_bounds__(1024) kcvt(
    const float* __restrict__ A, const float* __restrict__ B)
{
    const size_t i = (size_t)blockIdx.x * 1024 + threadIdx.x;
    if (i < 1048576) {
        const float4 v = ((const float4*)A)[i];
        ((uint2*)g_Ah)[i] = make_uint2(f22h2(v.x, v.y), f22h2(v.z, v.w));
    } else {
        const size_t j = i - 1048576;
        const float4 v = ((const float4*)B)[j];
        ((uint2*)g_Bh)[j] = make_uint2(f22h2(v.x, v.y), f22h2(v.z, v.w));
    }
    if (i < NB * L_SEQ) {
        g_Z[i] = 0.0f;
        g_W[i] = 0.0f;
    }
}

// ---------------------------------------------------------------------------
// K1: C = emb_h[8192,512] @ W_h[1536,512]^T + bias  (fp16 mma, NT)
// double-buffered smem, one sync per k-stage. Q stored pre-scaled by QSCALE.
// (R14 version — staged-store variant regressed, reverted.)
// ---------------------------------------------------------------------------
#define SA 40
__global__ void __launch_bounds__(256) k1_qkv(const float* __restrict__ bias)
{
    __shared__ __half As[2][128 * SA];
    __shared__ __half Bs[2][128 * SA];

    const int tid  = threadIdx.x;
    const int warp = tid >> 5;
    const int lane = tid & 31;
    const int g = lane >> 2, t = lane & 3;
    const int wm0 = (warp >> 2) * 64;
    const int wn0 = (warp & 3) * 32;
    const int m0 = blockIdx.y * 128;
    const int n0 = blockIdx.x * 128;

    const int lrow = tid >> 1;
    const int lk   = (tid & 1) * 16;
    const __half* ap = g_Ah + (size_t)(m0 + lrow) * EMB + lk;
    const __half* bp = g_Bh + (size_t)(n0 + lrow) * EMB + lk;

    const int lm = lane & 15;
    const int lc = (lane >> 4) * 8;

    float acc[4][4][4];
#pragma unroll
    for (int i = 0; i < 4; i++)
#pragma unroll
        for (int j = 0; j < 4; j++)
#pragma unroll
            for (int c = 0; c < 4; c++) acc[i][j][c] = 0.0f;

    uint4 a0 = *(const uint4*)(ap);
    uint4 a1 = *(const uint4*)(ap + 8);
    uint4 b0 = *(const uint4*)(bp);
    uint4 b1 = *(const uint4*)(bp + 8);
    *(uint4*)(As[0] + lrow * SA + lk)     = a0;
    *(uint4*)(As[0] + lrow * SA + lk + 8) = a1;
    *(uint4*)(Bs[0] + lrow * SA + lk)     = b0;
    *(uint4*)(Bs[0] + lrow * SA + lk + 8) = b1;

#pragma unroll 4
    for (int s = 0; s < 16; s++) {
        if (s < 15) {
            const int nk = (s + 1) * 32;
            a0 = *(const uint4*)(ap + nk);
            a1 = *(const uint4*)(ap + nk + 8);
            b0 = *(const uint4*)(bp + nk);
            b1 = *(const uint4*)(bp + nk + 8);
        }
        __syncthreads();
        const __half* Ab = As[s & 1];
        const __half* Bb = Bs[s & 1];
#pragma unroll
        for (int kk = 0; kk < 32; kk += 16) {
            uint32_t af[4][4];
#pragma unroll
            for (int im = 0; im < 4; im++)
                ldsm4(af[im][0], af[im][1], af[im][2], af[im][3],
                      Ab + (wm0 + im * 16 + lm) * SA + kk + lc);
            uint32_t br0[4], br1[4];
            ldsm4(br0[0], br0[1], br0[2], br0[3], Bb + (wn0 +      lm) * SA + kk + lc);
            ldsm4(br1[0], br1[1], br1[2], br1[3], Bb + (wn0 + 16 + lm) * SA + kk + lc);
            uint32_t bf[4][2] = {{br0[0], br0[2]}, {br0[1], br0[3]},
                                 {br1[0], br1[2]}, {br1[1], br1[3]}};
#pragma unroll
            for (int im = 0; im < 4; im++)
#pragma unroll
                for (int in = 0; in < 4; in++)
                    mma_f16(acc[im][in], af[im], bf[in]);
        }
        if (s < 15) {
            __half* An = As[(s + 1) & 1];
            __half* Bn = Bs[(s + 1) & 1];
            *(uint4*)(An + lrow * SA + lk)     = a0;
            *(uint4*)(An + lrow * SA + lk + 8) = a1;
            *(uint4*)(Bn + lrow * SA + lk)     = b0;
            *(uint4*)(Bn + lrow * SA + lk + 8) = b1;
        }
    }

#pragma unroll
    for (int im = 0; im < 4; im++) {
        const int r0 = m0 + wm0 + im * 16 + g;
#pragma unroll
        for (int in = 0; in < 4; in++) {
            const int c   = n0 + wn0 + in * 8 + 2 * t;
            const int h   = c / 192;
            const int rem = c - h * 192;
            const int sect = rem >> 6;
            const int d    = rem & 63;
            const float b0f = __ldg(bias + c), b1f = __ldg(bias + c + 1);
#pragma unroll
            for (int hf = 0; hf < 2; hf++) {
                const int r = r0 + hf * 8;
                const int l = r >> 3, bb = r & 7;
                const size_t off = ((size_t)(bb * 8 + h) << 16) + l * 64 + d;
                const float v0 = acc[im][in][2 * hf    ] + b0f;
                const float v1 = acc[im][in][2 * hf + 1] + b1f;
                if (sect == 0) {
                    *(uint32_t*)(g_Q + off) = f22h2(v0 * QSCALE, v1 * QSCALE);
                } else if (sect == 1) {
                    *(uint32_t*)(g_K + off) = f22h2(v0, v1);
                } else {
                    *(float2*)(g_V + off) = make_float2(v0, v1);
                }
            }
        }
    }
}

// ---------------------------------------------------------------------------
// K2: scores (log2 domain). Each CTA keeps its A tile (output rows) resident
// and sweeps TWO B tiles; reduce-mma accumulators carry across both, so
// atomics fire once per row. grid (4 B-pairs, 8 A-tiles, 64 B).
// PASS1: A=Q (rows=queries), B=K;  Z[row] += rowsum(exp2 S)  (ones-mma)
// PASS2: A=K (rows=keys),   B=Q;  W[row] += Σ_q exp2(S')*rZ[q] (rZ in B frag)
// ---------------------------------------------------------------------------
#define SQ 72
template<bool PASS2>
__global__ void __launch_bounds__(256) k2_attn()
{
    __shared__ __half Asm[128 * SQ];
    __shared__ __half Bsm[128 * SQ];
    __shared__ float  rsh[128];

    const int tid  = threadIdx.x;
    const int warp = tid >> 5;
    const int lane = tid & 31;
    const int g = lane >> 2, t = lane & 3;
    const int wm0 = (warp >> 2) * 64;
    const int wn0 = (warp & 3) * 32;

    const int B  = blockIdx.z;
    const int a0 = blockIdx.y * 128;        // A-tile rows (output rows)
    const int b0base = blockIdx.x * 256;    // two B tiles

    // load A tile (resident for both B-tile sweeps)
    const __half* ag = (PASS2 ? g_K : g_Q) + ((size_t)B << 16) + (size_t)a0 * 64;
#pragma unroll
    for (int j = 0; j < 4; j++) {
        const int idx = tid + j * 256;
        const int row = idx >> 3;
        const int ch  = (idx & 7) * 8;
        *(uint4*)(Asm + row * SQ + ch) = *(const uint4*)(ag + row * 64 + ch);
    }

    const int lm = lane & 15;
    const int lc = (lane >> 4) * 8;
    const uint32_t ones2 = 0x3C003C00u;

    float rs[4][4];
#pragma unroll
    for (int im = 0; im < 4; im++)
#pragma unroll
        for (int c = 0; c < 4; c++) rs[im][c] = 0.0f;

#pragma unroll
    for (int it = 0; it < 2; it++) {
        const int b0 = b0base + it * 128;
        const __half* bg = (PASS2 ? g_Q : g_K) + ((size_t)B << 16) + (size_t)b0 * 64;

        // prefetch B tile (and rZ for PASS2) into registers
        uint4 breg[4];
#pragma unroll
        for (int j = 0; j < 4; j++) {
            const int idx = tid + j * 256;
            const int row = idx >> 3;
            const int ch  = (idx & 7) * 8;
            breg[j] = *(const uint4*)(bg + row * 64 + ch);
        }
        float rznew = 0.0f;
        if (PASS2 && tid < 128)
            rznew = frcp(g_Z[B * 1024 + b0 + tid]);

        __syncthreads();   // prior iteration's Bsm/rsh reads complete
#pragma unroll
        for (int j = 0; j < 4; j++) {
            const int idx = tid + j * 256;
            const int row = idx >> 3;
            const int ch  = (idx & 7) * 8;
            *(uint4*)(Bsm + row * SQ + ch) = breg[j];
        }
        if (PASS2 && tid < 128)
            rsh[tid] = rznew;
        __syncthreads();   // Bsm/rsh (and Asm on it=0) visible

        // 128x128x64 score GEMM for this B tile
        float acc[4][4][4];
#pragma unroll
        for (int i = 0; i < 4; i++)
#pragma unroll
            for (int j = 0; j < 4; j++)
#pragma unroll
                for (int c = 0; c < 4; c++) acc[i][j][c] = 0.0f;

#pragma unroll
        for (int kk = 0; kk < 64; kk += 16) {
            uint32_t af[4][4];
#pragma unroll
            for (int im = 0; im < 4; im++)
                ldsm4(af[im][0], af[im][1], af[im][2], af[im][3],
                      Asm + (wm0 + im * 16 + lm) * SQ + kk + lc);
            uint32_t br0[4], br1[4];
            ldsm4(br0[0], br0[1], br0[2], br0[3], Bsm + (wn0 +      lm) * SQ + kk + lc);
            ldsm4(br1[0], br1[1], br1[2], br1[3], Bsm + (wn0 + 16 + lm) * SQ + kk + lc);
            uint32_t bf[4][2] = {{br0[0], br0[2]}, {br0[1], br0[3]},
                                 {br1[0], br1[2]}, {br1[1], br1[3]}};
#pragma unroll
            for (int im = 0; im < 4; im++)
#pragma unroll
                for (int in = 0; in < 4; in++)
                    mma_f16(acc[im][in], af[im], bf[in]);
        }

        // packed exp2 -> reduce-mma (accumulating into persistent rs)
        uint32_t eh[4][4][2];
#pragma unroll
        for (int im = 0; im < 4; im++)
#pragma unroll
            for (int in = 0; in < 4; in++) {
                eh[im][in][0] = ex2h2(acc[im][in][0], acc[im][in][1]);
                eh[im][in][1] = ex2h2(acc[im][in][2], acc[im][in][3]);
            }

        uint32_t bz0[2] = {ones2, ones2};
        uint32_t bz1[2] = {ones2, ones2};
        if (PASS2) {
            const int qb = wn0 + 2 * t;
            bz0[0] = f22h2(rsh[qb],      rsh[qb + 1]);
            bz0[1] = f22h2(rsh[qb + 8],  rsh[qb + 9]);
            bz1[0] = f22h2(rsh[qb + 16], rsh[qb + 17]);
            bz1[1] = f22h2(rsh[qb + 24], rsh[qb + 25]);
        }

#pragma unroll
        for (int im = 0; im < 4; im++) {
            uint32_t afr0[4] = {eh[im][0][0], eh[im][0][1], eh[im][1][0], eh[im][1][1]};
            mma_f16(rs[im], afr0, bz0);
            uint32_t afr1[4] = {eh[im][2][0], eh[im][2][1], eh[im][3][0], eh[im][3][1]};
            mma_f16(rs[im], afr1, bz1);
        }
    }

    float* target = PASS2 ? g_W : g_Z;
#pragma unroll
    for (int im = 0; im < 4; im++) {
        if (t == 0) {
            const int row = a0 + wm0 + im * 16 + g;
            atomicAdd(&target[B * 1024 + row],     rs[im][0]);
            atomicAdd(&target[B * 1024 + row + 8], rs[im][2]);
        }
    }
}

// ---------------------------------------------------------------------------
// K4a: partial dot products. grid (8 chunks, 64 B), block 256.
// ---------------------------------------------------------------------------
__global__ void __launch_bounds__(256) k4a_partial()
{
    const int B  = blockIdx.y;
    const int ch = blockIdx.x;
    const int tid = threadIdx.x;
    const int d = tid & 63, mg = tid >> 6;

    const float* vptr = g_V + ((size_t)B << 16) + (size_t)ch * 128 * 64 + d;
    const float* wp   = g_W + B * 1024 + ch * 128;

    float acc = 0.0f;
#pragma unroll 8
    for (int m = mg; m < 128; m += 4)
        acc = fmaf(wp[m], vptr[m * 64], acc);

    __shared__ float sh[4][64];
    sh[mg][d] = acc;
    __syncthreads();
    if (tid < 64)
        g_P[(B * 8 + ch) * 64 + tid] =
            sh[0][tid] + sh[1][tid] + sh[2][tid] + sh[3][tid];
}

// ---------------------------------------------------------------------------
// K4b: reduce 8 partials + GroupNorm + affine + out. grid 64, block 64.
// ---------------------------------------------------------------------------
__global__ void __launch_bounds__(64) k4b_gn(
    const float* __restrict__ gw, const float* __restrict__ gb,
    float* __restrict__ out)
{
    const int B  = blockIdx.x;
    const int bb = B >> 3, hh = B & 7;
    const int tid = threadIdx.x;
    const int lane = tid & 31, wp = tid >> 5;

    float v = 0.0f;
#pragma unroll
    for (int c = 0; c < 8; c++)
        v += g_P[(B * 8 + c) * 64 + tid];

    float s = v, sq = v * v;
#pragma unroll
    for (int o = 16; o > 0; o >>= 1) {
        s  += __shfl_xor_sync(0xffffffffu, s, o);
        sq += __shfl_xor_sync(0xffffffffu, sq, o);
    }
    __shared__ float red[4];
    if (lane == 0) { red[wp * 2] = s; red[wp * 2 + 1] = sq; }
    __syncthreads();
    const float sum = red[0] + red[2];
    const float ssq = red[1] + red[3];
    const float mean = sum * (1.0f / 64.0f);
    const float var  = ssq * (1.0f / 64.0f) - mean * mean;
    out[bb * 512 + hh * 64 + tid] =
        (v - mean) * rsqrtf(var + 1e-5f) * __ldg(gw + hh) + __ldg(gb + hh);
}

// ---------------------------------------------------------------------------
// Launcher (graph-capturable)
// ---------------------------------------------------------------------------
extern "C" void kernel_launch(void* const* d_in, const int* in_sizes, int n_in,
                              void* d_out, int out_size)
{
    (void)in_sizes; (void)n_in; (void)out_size;
    const float* emb = (const float*)d_in[0];
    const float* Wq  = (const float*)d_in[1];
    const float* bq  = (const float*)d_in[2];
    const float* gw  = (const float*)d_in[3];
    const float* gb  = (const float*)d_in[4];
    float* out = (float*)d_out;

    kcvt     <<<1216, 1024>>>(emb, Wq);
    k1_qkv   <<<dim3(12, 64), 256>>>(bq);
    k2_attn<false><<<dim3(4, 8, 64), 256>>>();
    k2_attn<true> <<<dim3(4, 8, 64), 256>>>();
    k4a_partial<<<dim3(8, 64), 256>>>();
    k4b_gn   <<<64, 64>>>(gw, gb, out);
}

// round 17
// speedup vs baseline: 1.1186x; 1.0275x over previous
#include <cuda_runtime.h>
#include <cuda_fp16.h>
#include <cstdint>

#define L_SEQ 1024
#define BATCH_BS 8
#define EMB 512
#define O3 1536
#define NB 64            // BATCH_BS * NH

// Q pre-scale: exp(0.125*s) = exp2(s * 0.125 * log2(e))
#define QSCALE 0.18033688011112042f

// Scratch (device globals)
__device__ __half g_Ah[(size_t)8192 * EMB];       // emb as fp16, 8 MB
__device__ __half g_Bh[(size_t)O3 * EMB];         // W_qkv as fp16, 1.5 MB
__device__ __half g_Q[(size_t)NB * L_SEQ * 64];   // 8 MB (pre-scaled by QSCALE)
__device__ __half g_K[(size_t)NB * L_SEQ * 64];   // 8 MB
__device__ float  g_V[(size_t)NB * L_SEQ * 64];   // 16 MB
__device__ float  g_Z[NB * L_SEQ];                // raw row sums (atomic)
__device__ float  g_W[NB * L_SEQ];                // attn weights (atomic)
__device__ float  g_P[NB * 8 * 64];               // k4a partials

// ---------------------------------------------------------------------------
// helpers
// ---------------------------------------------------------------------------
__device__ __forceinline__ uint32_t f22h2(float lo, float hi) {
    __half2 h = __floats2half2_rn(lo, hi);
    return reinterpret_cast<uint32_t&>(h);
}
__device__ __forceinline__ uint32_t smem_u32(const void* p) {
    return (uint32_t)__cvta_generic_to_shared(p);
}
__device__ __forceinline__ float frcp(float x) {
    float r;
    asm("rcp.approx.f32 %0, %1;" : "=f"(r) : "f"(x));
    return r;
}
// exp2 on an ALREADY-PACKED fp16x2 register: one MUFU op, two exps, no cvts
__device__ __forceinline__ uint32_t ex2u(uint32_t p) {
    uint32_t e;
    asm("ex2.approx.f16x2 %0, %1;" : "=r"(e) : "r"(p));
    return e;
}
__device__ __forceinline__ void ldsm4(uint32_t& r0, uint32_t& r1,
                                      uint32_t& r2, uint32_t& r3,
                                      const __half* p) {
    uint32_t addr = smem_u32(p);
    asm volatile("ldmatrix.sync.aligned.m8n8.x4.shared.b16 {%0,%1,%2,%3}, [%4];"
                 : "=r"(r0), "=r"(r1), "=r"(r2), "=r"(r3) : "r"(addr));
}
// fp32-accumulate mma (k1 + reduce-mmas)
__device__ __forceinline__ void mma_f16(float* d, const uint32_t* a, const uint32_t* b) {
    asm volatile(
        "mma.sync.aligned.m16n8k16.row.col.f32.f16.f16.f32 "
        "{%0,%1,%2,%3}, {%4,%5,%6,%7}, {%8,%9}, {%0,%1,%2,%3};\n"
        : "+f"(d[0]), "+f"(d[1]), "+f"(d[2]), "+f"(d[3])
        : "r"(a[0]), "r"(a[1]), "r"(a[2]), "r"(a[3]), "r"(b[0]), "r"(b[1]));
}
// fp16-accumulate mma (score GEMM — full rate, D packed as h2 pairs)
__device__ __forceinline__ void mma_f16acc(uint32_t* d, const uint32_t* a, const uint32_t* b) {
    asm volatile(
        "mma.sync.aligned.m16n8k16.row.col.f16.f16.f16.f16 "
        "{%0,%1}, {%2,%3,%4,%5}, {%6,%7}, {%0,%1};\n"
        : "+r"(d[0]), "+r"(d[1])
        : "r"(a[0]), "r"(a[1]), "r"(a[2]), "r"(a[3]), "r"(b[0]), "r"(b[1]));
}

// ---------------------------------------------------------------------------
// KC: one-time fp32 -> fp16 convert of emb + W_qkv; zero Z and W.
// ---------------------------------------------------------------------------
__global__ void __launch_bounds__(1024) kcvt(
    const float* __restrict__ A, const float* __restrict__ B)
{
    const size_t i = (size_t)blockIdx.x * 1024 + threadIdx.x;
    if (i < 1048576) {
        const float4 v = ((const float4*)A)[i];
        ((uint2*)g_Ah)[i] = make_uint2(f22h2(v.x, v.y), f22h2(v.z, v.w));
    } else {
        const size_t j = i - 1048576;
        const float4 v = ((const float4*)B)[j];
        ((uint2*)g_Bh)[j] = make_uint2(f22h2(v.x, v.y), f22h2(v.z, v.w));
    }
    if (i < NB * L_SEQ) {
        g_Z[i] = 0.0f;
        g_W[i] = 0.0f;
    }
}

// ---------------------------------------------------------------------------
// K1: C = emb_h[8192,512] @ W_h[1536,512]^T + bias  (fp16 mma, fp32 acc, NT)
// double-buffered smem, one sync per k-stage. Q stored pre-scaled by QSCALE.
// ---------------------------------------------------------------------------
#define SA 40
__global__ void __launch_bounds__(256) k1_qkv(const float* __restrict__ bias)
{
    __shared__ __half As[2][128 * SA];
    __shared__ __half Bs[2][128 * SA];

    const int tid  = threadIdx.x;
    const int warp = tid >> 5;
    const int lane = tid & 31;
    const int g = lane >> 2, t = lane & 3;
    const int wm0 = (warp >> 2) * 64;
    const int wn0 = (warp & 3) * 32;
    const int m0 = blockIdx.y * 128;
    const int n0 = blockIdx.x * 128;

    const int lrow = tid >> 1;
    const int lk   = (tid & 1) * 16;
    const __half* ap = g_Ah + (size_t)(m0 + lrow) * EMB + lk;
    const __half* bp = g_Bh + (size_t)(n0 + lrow) * EMB + lk;

    const int lm = lane & 15;
    const int lc = (lane >> 4) * 8;

    float acc[4][4][4];
#pragma unroll
    for (int i = 0; i < 4; i++)
#pragma unroll
        for (int j = 0; j < 4; j++)
#pragma unroll
            for (int c = 0; c < 4; c++) acc[i][j][c] = 0.0f;

    uint4 a0 = *(const uint4*)(ap);
    uint4 a1 = *(const uint4*)(ap + 8);
    uint4 b0 = *(const uint4*)(bp);
    uint4 b1 = *(const uint4*)(bp + 8);
    *(uint4*)(As[0] + lrow * SA + lk)     = a0;
    *(uint4*)(As[0] + lrow * SA + lk + 8) = a1;
    *(uint4*)(Bs[0] + lrow * SA + lk)     = b0;
    *(uint4*)(Bs[0] + lrow * SA + lk + 8) = b1;

#pragma unroll 4
    for (int s = 0; s < 16; s++) {
        if (s < 15) {
            const int nk = (s + 1) * 32;
            a0 = *(const uint4*)(ap + nk);
            a1 = *(const uint4*)(ap + nk + 8);
            b0 = *(const uint4*)(bp + nk);
            b1 = *(const uint4*)(bp + nk + 8);
        }
        __syncthreads();
        const __half* Ab = As[s & 1];
        const __half* Bb = Bs[s & 1];
#pragma unroll
        for (int kk = 0; kk < 32; kk += 16) {
            uint32_t af[4][4];
#pragma unroll
            for (int im = 0; im < 4; im++)
                ldsm4(af[im][0], af[im][1], af[im][2], af[im][3],
                      Ab + (wm0 + im * 16 + lm) * SA + kk + lc);
            uint32_t br0[4], br1[4];
            ldsm4(br0[0], br0[1], br0[2], br0[3], Bb + (wn0 +      lm) * SA + kk + lc);
            ldsm4(br1[0], br1[1], br1[2], br1[3], Bb + (wn0 + 16 + lm) * SA + kk + lc);
            uint32_t bf[4][2] = {{br0[0], br0[2]}, {br0[1], br0[3]},
                                 {br1[0], br1[2]}, {br1[1], br1[3]}};
#pragma unroll
            for (int im = 0; im < 4; im++)
#pragma unroll
                for (int in = 0; in < 4; in++)
                    mma_f16(acc[im][in], af[im], bf[in]);
        }
        if (s < 15) {
            __half* An = As[(s + 1) & 1];
            __half* Bn = Bs[(s + 1) & 1];
            *(uint4*)(An + lrow * SA + lk)     = a0;
            *(uint4*)(An + lrow * SA + lk + 8) = a1;
            *(uint4*)(Bn + lrow * SA + lk)     = b0;
            *(uint4*)(Bn + lrow * SA + lk + 8) = b1;
        }
    }

#pragma unroll
    for (int im = 0; im < 4; im++) {
        const int r0 = m0 + wm0 + im * 16 + g;
#pragma unroll
        for (int in = 0; in < 4; in++) {
            const int c   = n0 + wn0 + in * 8 + 2 * t;
            const int h   = c / 192;
            const int rem = c - h * 192;
            const int sect = rem >> 6;
            const int d    = rem & 63;
            const float b0f = __ldg(bias + c), b1f = __ldg(bias + c + 1);
#pragma unroll
            for (int hf = 0; hf < 2; hf++) {
                const int r = r0 + hf * 8;
                const int l = r >> 3, bb = r & 7;
                const size_t off = ((size_t)(bb * 8 + h) << 16) + l * 64 + d;
                const float v0 = acc[im][in][2 * hf    ] + b0f;
                const float v1 = acc[im][in][2 * hf + 1] + b1f;
                if (sect == 0) {
                    *(uint32_t*)(g_Q + off) = f22h2(v0 * QSCALE, v1 * QSCALE);
                } else if (sect == 1) {
                    *(uint32_t*)(g_K + off) = f22h2(v0, v1);
                } else {
                    *(float2*)(g_V + off) = make_float2(v0, v1);
                }
            }
        }
    }
}

// ---------------------------------------------------------------------------
// K2: scores (log2 domain) with FP16 ACCUMULATORS (full-rate HMMA).
// Each CTA keeps its A tile resident and sweeps TWO B tiles; reduce-mma
// accumulators (fp32) carry across both, atomics fire once per row.
// D registers are packed h2 pairs -> ex2.approx.f16x2 applies DIRECTLY.
// PASS1: A=Q, B=K; Z[row] += rowsum(exp2 S)  (ones-mma)
// PASS2: A=K, B=Q; W[row] += Σ_q exp2(S')*rZ[q]  (rZ carried in B fragment)
// ---------------------------------------------------------------------------
#define SQ 72
template<bool PASS2>
__global__ void __launch_bounds__(256) k2_attn()
{
    __shared__ __half Asm[128 * SQ];
    __shared__ __half Bsm[128 * SQ];
    __shared__ float  rsh[128];

    const int tid  = threadIdx.x;
    const int warp = tid >> 5;
    const int lane = tid & 31;
    const int g = lane >> 2, t = lane & 3;
    const int wm0 = (warp >> 2) * 64;
    const int wn0 = (warp & 3) * 32;

    const int B  = blockIdx.z;
    const int a0 = blockIdx.y * 128;
    const int b0base = blockIdx.x * 256;

    const __half* ag = (PASS2 ? g_K : g_Q) + ((size_t)B << 16) + (size_t)a0 * 64;
#pragma unroll
    for (int j = 0; j < 4; j++) {
        const int idx = tid + j * 256;
        const int row = idx >> 3;
        const int ch  = (idx & 7) * 8;
        *(uint4*)(Asm + row * SQ + ch) = *(const uint4*)(ag + row * 64 + ch);
    }

    const int lm = lane & 15;
    const int lc = (lane >> 4) * 8;
    const uint32_t ones2 = 0x3C003C00u;

    float rs[4][4];
#pragma unroll
    for (int im = 0; im < 4; im++)
#pragma unroll
        for (int c = 0; c < 4; c++) rs[im][c] = 0.0f;

#pragma unroll
    for (int it = 0; it < 2; it++) {
        const int b0 = b0base + it * 128;
        const __half* bg = (PASS2 ? g_Q : g_K) + ((size_t)B << 16) + (size_t)b0 * 64;

        uint4 breg[4];
#pragma unroll
        for (int j = 0; j < 4; j++) {
            const int idx = tid + j * 256;
            const int row = idx >> 3;
            const int ch  = (idx & 7) * 8;
            breg[j] = *(const uint4*)(bg + row * 64 + ch);
        }
        float rznew = 0.0f;
        if (PASS2 && tid < 128)
            rznew = frcp(g_Z[B * 1024 + b0 + tid]);

        __syncthreads();
#pragma unroll
        for (int j = 0; j < 4; j++) {
            const int idx = tid + j * 256;
            const int row = idx >> 3;
            const int ch  = (idx & 7) * 8;
            *(uint4*)(Bsm + row * SQ + ch) = breg[j];
        }
        if (PASS2 && tid < 128)
            rsh[tid] = rznew;
        __syncthreads();

        // 128x128x64 score GEMM, fp16 accumulators (packed h2 output)
        uint32_t hacc[4][4][2];
#pragma unroll
        for (int i = 0; i < 4; i++)
#pragma unroll
            for (int j = 0; j < 4; j++) { hacc[i][j][0] = 0u; hacc[i][j][1] = 0u; }

#pragma unroll
        for (int kk = 0; kk < 64; kk += 16) {
            uint32_t af[4][4];
#pragma unroll
            for (int im = 0; im < 4; im++)
                ldsm4(af[im][0], af[im][1], af[im][2], af[im][3],
                      Asm + (wm0 + im * 16 + lm) * SQ + kk + lc);
            uint32_t br0[4], br1[4];
            ldsm4(br0[0], br0[1], br0[2], br0[3], Bsm + (wn0 +      lm) * SQ + kk + lc);
            ldsm4(br1[0], br1[1], br1[2], br1[3], Bsm + (wn0 + 16 + lm) * SQ + kk + lc);
            uint32_t bf[4][2] = {{br0[0], br0[2]}, {br0[1], br0[3]},
                                 {br1[0], br1[2]}, {br1[1], br1[3]}};
#pragma unroll
            for (int im = 0; im < 4; im++)
#pragma unroll
                for (int in = 0; in < 4; in++)
                    mma_f16acc(hacc[im][in], af[im], bf[in]);
        }

        // exp2 directly on packed accumulators -> reduce-mma (fp32 acc)
        uint32_t bz0[2] = {ones2, ones2};
        uint32_t bz1[2] = {ones2, ones2};
        if (PASS2) {
            const int qb = wn0 + 2 * t;
            bz0[0] = f22h2(rsh[qb],      rsh[qb + 1]);
            bz0[1] = f22h2(rsh[qb + 8],  rsh[qb + 9]);
            bz1[0] = f22h2(rsh[qb + 16], rsh[qb + 17]);
            bz1[1] = f22h2(rsh[qb + 24], rsh[qb + 25]);
        }

#pragma unroll
        for (int im = 0; im < 4; im++) {
            uint32_t afr0[4] = {ex2u(hacc[im][0][0]), ex2u(hacc[im][0][1]),
                                ex2u(hacc[im][1][0]), ex2u(hacc[im][1][1])};
            mma_f16(rs[im], afr0, bz0);
            uint32_t afr1[4] = {ex2u(hacc[im][2][0]), ex2u(hacc[im][2][1]),
                                ex2u(hacc[im][3][0]), ex2u(hacc[im][3][1])};
            mma_f16(rs[im], afr1, bz1);
        }
    }

    float* target = PASS2 ? g_W : g_Z;
#pragma unroll
    for (int im = 0; im < 4; im++) {
        if (t == 0) {
            const int row = a0 + wm0 + im * 16 + g;
            atomicAdd(&target[B * 1024 + row],     rs[im][0]);
            atomicAdd(&target[B * 1024 + row + 8], rs[im][2]);
        }
    }
}

// ---------------------------------------------------------------------------
// K4a: partial dot products. grid (8 chunks, 64 B), block 256.
// ---------------------------------------------------------------------------
__global__ void __launch_bounds__(256) k4a_partial()
{
    const int B  = blockIdx.y;
    const int ch = blockIdx.x;
    const int tid = threadIdx.x;
    const int d = tid & 63, mg = tid >> 6;

    const float* vptr = g_V + ((size_t)B << 16) + (size_t)ch * 128 * 64 + d;
    const float* wp   = g_W + B * 1024 + ch * 128;

    float acc = 0.0f;
#pragma unroll 8
    for (int m = mg; m < 128; m += 4)
        acc = fmaf(wp[m], vptr[m * 64], acc);

    __shared__ float sh[4][64];
    sh[mg][d] = acc;
    __syncthreads();
    if (tid < 64)
        g_P[(B * 8 + ch) * 64 + tid] =
            sh[0][tid] + sh[1][tid] + sh[2][tid] + sh[3][tid];
}

// ---------------------------------------------------------------------------
// K4b: reduce 8 partials + GroupNorm + affine + out. grid 64, block 64.
// ---------------------------------------------------------------------------
__global__ void __launch_bounds__(64) k4b_gn(
    const float* __restrict__ gw, const float* __restrict__ gb,
    float* __restrict__ out)
{
    const int B  = blockIdx.x;
    const int bb = B >> 3, hh = B & 7;
    const int tid = threadIdx.x;
    const int lane = tid & 31, wp = tid >> 5;

    float v = 0.0f;
#pragma unroll
    for (int c = 0; c < 8; c++)
        v += g_P[(B * 8 + c) * 64 + tid];

    float s = v, sq = v * v;
#pragma unroll
    for (int o = 16; o > 0; o >>= 1) {
        s  += __shfl_xor_sync(0xffffffffu, s, o);
        sq += __shfl_xor_sync(0xffffffffu, sq, o);
    }
    __shared__ float red[4];
    if (lane == 0) { red[wp * 2] = s; red[wp * 2 + 1] = sq; }
    __syncthreads();
    const float sum = red[0] + red[2];
    const float ssq = red[1] + red[3];
    const float mean = sum * (1.0f / 64.0f);
    const float var  = ssq * (1.0f / 64.0f) - mean * mean;
    out[bb * 512 + hh * 64 + tid] =
        (v - mean) * rsqrtf(var + 1e-5f) * __ldg(gw + hh) + __ldg(gb + hh);
}

// ---------------------------------------------------------------------------
// Launcher (graph-capturable)
// ---------------------------------------------------------------------------
extern "C" void kernel_launch(void* const* d_in, const int* in_sizes, int n_in,
                              void* d_out, int out_size)
{
    (void)in_sizes; (void)n_in; (void)out_size;
    const float* emb = (const float*)d_in[0];
    const float* Wq  = (const float*)d_in[1];
    const float* bq  = (const float*)d_in[2];
    const float* gw  = (const float*)d_in[3];
    const float* gb  = (const float*)d_in[4];
    float* out = (float*)d_out;

    kcvt     <<<1216, 1024>>>(emb, Wq);
    k1_qkv   <<<dim3(12, 64), 256>>>(bq);
    k2_attn<false><<<dim3(4, 8, 64), 256>>>();
    k2_attn<true> <<<dim3(4, 8, 64), 256>>>();
    k4a_partial<<<dim3(8, 64), 256>>>();
    k4b_gn   <<<64, 64>>>(gw, gb, out);
}